// round 1
// baseline (speedup 1.0000x reference)
#include <cuda_runtime.h>
#include <cuda_bf16.h>
#include <math.h>

// ---------------- problem constants ----------------
#define PK      12          // K
#define PKQ     6           // K_Q
#define PH      64          // H
#define PD      768         // D
#define DIM_MEM 768         // K*H
#define DIM_MEM_TOT 780     // +K
#define DIM_CONV 1548
#define OUT_CPLX 1536
#define DIM_EXPAND 192
#define PMAXLEN 4096
#define PKSIZE  4
#define PB      4
#define PL      4096
#define NTOK    (PB*PL)     // 16384
#define NCHUNK  8
#define CHROWS  (PL/NCHUNK) // 512

// ---------------- device scratch -------------------
__device__ float g_buf0[(size_t)NTOK*DIM_CONV];   // z_pre, then stack/cumsum
__device__ float g_z   [(size_t)NTOK*DIM_CONV];   // conv+silu output
__device__ float g_outn[(size_t)NTOK*OUT_CPLX];   // normalized out
__device__ float g_gate[(size_t)NTOK*OUT_CPLX];   // x @ W_gate
__device__ float g_yraw[(size_t)NTOK*(PK*384)];   // readout raw
__device__ float g_y   [(size_t)NTOK*(PK*DIM_EXPAND)]; // gated readout
__device__ float g_csum[(size_t)PB*NCHUNK*DIM_CONV];   // chunk sums -> offsets
__device__ float g_theta[PK*PH];
__device__ float g_wint [PK*PH];
__device__ float g_slope[PK];

// ---------------- helpers --------------------------
__device__ __forceinline__ float sigmoidf_(float x){ return 1.f/(1.f+expf(-x)); }
__device__ __forceinline__ float softplusf_(float x){ return (x>20.f)? x : log1pf(expf(x)); }

// ---------------- small precompute ------------------
__global__ void prep_kernel(const float* __restrict__ theta_raw,
                            const float* __restrict__ wint_raw,
                            const float* __restrict__ decay)
{
    int i = threadIdx.x;
    if (i < PK*PH) {
        g_theta[i] = 0.001f + 2.999f * sigmoidf_(theta_raw[i]);
        float e = expf(wint_raw[i]);
        g_wint[i] = e / (e + 1e-6f);
    }
    if (i < PK) g_slope[i] = softplusf_(decay[i]);
}

// ---------------- generic batched SGEMM -------------
// C[M,N] = A[M,K] * B[K,N], row-major, fp32. M%128==0, K%16==0, N%4==0.
#define BM 128
#define BN 128
#define BKD 16
#define TM 8
#define TN 8

__global__ void __launch_bounds__(256, 2)
sgemm_kernel(int M, int N, int Kd,
             const float* __restrict__ A, int lda, long long sA,
             const float* __restrict__ B, int ldb, long long sB,
             float* __restrict__ C, int ldc, long long sC)
{
    __shared__ float As[BKD][BM+4];
    __shared__ float Bs[BKD][BN];

    int zb = blockIdx.z;
    A += (long long)zb * sA;
    B += (long long)zb * sB;
    C += (long long)zb * sC;

    const int tile_n = blockIdx.x * BN;
    const int tile_m = blockIdx.y * BM;
    const int tid = threadIdx.x;
    const int tx = tid & 15;
    const int ty = tid >> 4;

    float acc[TM][TN];
#pragma unroll
    for (int i = 0; i < TM; i++)
#pragma unroll
        for (int j = 0; j < TN; j++) acc[i][j] = 0.f;

    for (int k0 = 0; k0 < Kd; k0 += BKD) {
        // A tile -> transposed smem
#pragma unroll
        for (int i = 0; i < 2; i++) {
            int lin = tid + i*256;
            int row = lin >> 2;
            int kq  = (lin & 3) << 2;
            const float4 v = *(const float4*)(A + (long long)(tile_m + row)*lda + k0 + kq);
            As[kq+0][row] = v.x;
            As[kq+1][row] = v.y;
            As[kq+2][row] = v.z;
            As[kq+3][row] = v.w;
        }
        // B tile
#pragma unroll
        for (int i = 0; i < 2; i++) {
            int lin = tid + i*256;
            int kr = lin >> 5;
            int c4 = (lin & 31) << 2;
            int gcol = tile_n + c4;
            float4 v = make_float4(0.f,0.f,0.f,0.f);
            if (gcol < N)
                v = *(const float4*)(B + (long long)(k0+kr)*ldb + gcol);
            *(float4*)&Bs[kr][c4] = v;
        }
        __syncthreads();

#pragma unroll
        for (int kk = 0; kk < BKD; kk++) {
            float aF[TM], bF[TN];
#pragma unroll
            for (int i = 0; i < TM; i++) aF[i] = As[kk][ty*TM + i];
#pragma unroll
            for (int j = 0; j < TN; j++) bF[j] = Bs[kk][tx*TN + j];
#pragma unroll
            for (int i = 0; i < TM; i++)
#pragma unroll
                for (int j = 0; j < TN; j++)
                    acc[i][j] = fmaf(aF[i], bF[j], acc[i][j]);
        }
        __syncthreads();
    }

#pragma unroll
    for (int i = 0; i < TM; i++) {
        long long row = tile_m + ty*TM + i;
        float* Crow = C + row*(long long)ldc;
#pragma unroll
        for (int j4 = 0; j4 < TN; j4 += 4) {
            int col = tile_n + tx*TN + j4;
            if (col < N) {
                *(float4*)(Crow + col) = make_float4(acc[i][j4], acc[i][j4+1],
                                                     acc[i][j4+2], acc[i][j4+3]);
            }
        }
    }
}

// ---------------- causal depthwise conv + silu ------
__global__ void conv_silu_kernel(const float* __restrict__ conv_w)
{
    int c = blockIdx.x * blockDim.x + threadIdx.x;
    if (c >= DIM_CONV) return;
    int tok = blockIdx.y;
    int l = tok & (PL-1);

    long long base = (long long)tok * DIM_CONV + c;
    float acc = 0.f;
#pragma unroll
    for (int t = 0; t < PKSIZE; t++) {
        int dl = l + t - (PKSIZE-1);
        if (dl >= 0)
            acc += g_buf0[base + (long long)(t - (PKSIZE-1)) * DIM_CONV] * conv_w[t*DIM_CONV + c];
    }
    g_z[base] = acc * sigmoidf_(acc);
}

// ---------------- stack builder ---------------------
// stack[tok] = [p_w(12), re(768), im(768)]
__global__ void stack_kernel(const float* __restrict__ score_scale,
                             const float* __restrict__ score_bias,
                             const float* __restrict__ phase_scale)
{
    __shared__ float s_pw[PK];
    int tok = blockIdx.x;
    int tid = threadIdx.x;
    int l = tok & (PL-1);
    long long zb = (long long)tok * DIM_CONV;

    if (tid < PK) {
        float s  = g_z[zb + DIM_MEM + tid];
        float u  = score_scale[tid]*s + score_bias[tid];
        float sp = softplusf_(u);
        float tw = expf(-g_slope[tid] * (float)(PMAXLEN-1 - l));
        float p  = fminf(fmaxf(sp*tw, 1e-4f), 5000.f);
        s_pw[tid] = p;
        g_buf0[zb + tid] = p;
    }
    __syncthreads();

    for (int i = tid; i < DIM_MEM; i += blockDim.x) {
        int k = i >> 6;
        float kv = g_z[zb + i];
        float ks = kv * phase_scale[k];
        float phi = ks / (1.f + fabsf(ks)) * g_theta[i];
        float sn, cs;
        sincosf(phi, &sn, &cs);
        float kvw = kv * s_pw[k];
        g_buf0[zb + PK + i]           = kvw * cs;
        g_buf0[zb + PK + DIM_MEM + i] = kvw * sn;
    }
}

// ---------------- chunked scan ----------------------
__global__ void scan_partial_kernel()
{
    int c = blockIdx.x * blockDim.x + threadIdx.x;
    if (c >= DIM_CONV) return;
    int chunk = blockIdx.y;
    int b = blockIdx.z;

    long long base = ((long long)(b*PL + chunk*CHROWS)) * DIM_CONV + c;
    float run = 0.f;
#pragma unroll 4
    for (int r = 0; r < CHROWS; r++) {
        long long p = base + (long long)r * DIM_CONV;
        run += g_buf0[p];
        g_buf0[p] = run;
    }
    g_csum[((long long)(b*NCHUNK + chunk))*DIM_CONV + c] = run;
}

__global__ void scan_offsets_kernel()
{
    int i = blockIdx.x * blockDim.x + threadIdx.x;
    if (i >= PB*DIM_CONV) return;
    int b = i / DIM_CONV;
    int c = i - b*DIM_CONV;
    float off = 0.f;
#pragma unroll
    for (int ch = 0; ch < NCHUNK; ch++) {
        long long idx = ((long long)(b*NCHUNK + ch))*DIM_CONV + c;
        float t = g_csum[idx];
        g_csum[idx] = off;      // exclusive prefix
        off += t;
    }
}

// ---------------- epilogue 1: out_flat + gated rmsnorm
__global__ void epilogue1_kernel(const float* __restrict__ gnw)
{
    __shared__ float s_inv[PK];
    __shared__ float s_red[8];
    int tok = blockIdx.x;
    int tid = threadIdx.x;
    int l = tok & (PL-1);
    int b = tok >> 12;
    int chunk = l >> 9;  // l / 512

    long long zb  = (long long)tok * DIM_CONV;
    long long ob  = ((long long)(b*NCHUNK + chunk)) * DIM_CONV;
    long long gb  = (long long)tok * OUT_CPLX;

    if (tid < PK) {
        float den = g_buf0[zb + tid] + g_csum[ob + tid];
        s_inv[tid] = 1.f / fmaxf(den, 1e-4f);
    }
    __syncthreads();

    float hvals[OUT_CPLX/256];
    float sumsq = 0.f;
#pragma unroll
    for (int it = 0; it < OUT_CPLX/256; it++) {
        int f = tid + it*256;
        int k = f >> 7;
        int j = f & 127;
        int h = j & 63;
        int is_im = j >> 6;
        int idx = k*PH + h;

        float re_acc = g_buf0[zb + PK + idx]           + g_csum[ob + PK + idx];
        float im_acc = g_buf0[zb + PK + DIM_MEM + idx] + g_csum[ob + PK + DIM_MEM + idx];
        float sre = re_acc * s_inv[k];
        float sim = im_acc * s_inv[k];
        int kq = k >> 1;
        float qre = g_z[zb + DIM_MEM_TOT + (kq*PH + h)*2];
        float qim = g_z[zb + DIM_MEM_TOT + (kq*PH + h)*2 + 1];
        float val;
        if (!is_im) val = (sre*qre + sim*qim);
        else        val = (sim*qre - sre*qim);
        val *= 0.125f * g_wint[idx];   // H^-0.5 = 1/8

        float gv = g_gate[gb + f];
        float hv = val * (gv * sigmoidf_(gv));
        hvals[it] = hv;
        sumsq += hv*hv;
    }
    // block reduction
#pragma unroll
    for (int o = 16; o > 0; o >>= 1) sumsq += __shfl_xor_sync(0xffffffff, sumsq, o);
    if ((tid & 31) == 0) s_red[tid >> 5] = sumsq;
    __syncthreads();
    if (tid < 32) {
        float v = (tid < 8) ? s_red[tid] : 0.f;
#pragma unroll
        for (int o = 4; o > 0; o >>= 1) v += __shfl_xor_sync(0xffffffff, v, o);
        if (tid == 0) s_red[0] = v;
    }
    __syncthreads();
    float rms = rsqrtf(s_red[0] / (float)OUT_CPLX + 1e-6f);

#pragma unroll
    for (int it = 0; it < OUT_CPLX/256; it++) {
        int f = tid + it*256;
        g_outn[gb + f] = hvals[it] * rms * gnw[f];
    }
}

// ---------------- readout gating --------------------
__global__ void ygate_kernel()
{
    int j = blockIdx.x * blockDim.x + threadIdx.x;
    if (j >= PK*DIM_EXPAND) return;
    int tok = blockIdx.y;
    int k = j / DIM_EXPAND;
    int n = j - k*DIM_EXPAND;
    long long yb = (long long)tok * (PK*384);
    float v = g_yraw[yb + k*384 + n];
    float g = g_yraw[yb + k*384 + DIM_EXPAND + n];
    g_y[(long long)tok*(PK*DIM_EXPAND) + j] = v * sigmoidf_(g);
}

// ---------------- launcher --------------------------
extern "C" void kernel_launch(void* const* d_in, const int* in_sizes, int n_in,
                              void* d_out, int out_size)
{
    const float* x        = (const float*)d_in[0];
    const float* W_in     = (const float*)d_in[1];
    const float* conv_w   = (const float*)d_in[2];
    const float* theta_raw= (const float*)d_in[3];
    const float* wint_raw = (const float*)d_in[4];
    const float* decay    = (const float*)d_in[5];
    const float* sscale   = (const float*)d_in[6];
    const float* sbias    = (const float*)d_in[7];
    const float* pscale   = (const float*)d_in[8];
    const float* gnw      = (const float*)d_in[9];
    const float* W_read   = (const float*)d_in[10];
    const float* W_gate   = (const float*)d_in[11];
    const float* W_out    = (const float*)d_in[12];
    float* out            = (float*)d_out;

    float *p_buf0, *p_z, *p_outn, *p_gate, *p_yraw, *p_y;
    cudaGetSymbolAddress((void**)&p_buf0, g_buf0);
    cudaGetSymbolAddress((void**)&p_z,    g_z);
    cudaGetSymbolAddress((void**)&p_outn, g_outn);
    cudaGetSymbolAddress((void**)&p_gate, g_gate);
    cudaGetSymbolAddress((void**)&p_yraw, g_yraw);
    cudaGetSymbolAddress((void**)&p_y,    g_y);

    // 0) tiny precompute
    prep_kernel<<<1, 768>>>(theta_raw, wint_raw, decay);

    // 1) z_pre = x @ W_in   [16384,1548]
    sgemm_kernel<<<dim3((DIM_CONV+BN-1)/BN, NTOK/BM, 1), 256>>>(
        NTOK, DIM_CONV, PD, x, PD, 0, W_in, DIM_CONV, 0, p_buf0, DIM_CONV, 0);

    // 2) conv + silu -> z
    conv_silu_kernel<<<dim3((DIM_CONV+255)/256, NTOK), 256>>>(conv_w);

    // 3) build stack (overwrites g_buf0)
    stack_kernel<<<NTOK, 256>>>(sscale, sbias, pscale);

    // 4) chunked cumsum over L (in-place, offsets kept separate)
    scan_partial_kernel<<<dim3((DIM_CONV+127)/128, NCHUNK, PB), 128>>>();
    scan_offsets_kernel<<<(PB*DIM_CONV+255)/256, 256>>>();

    // 5) gate = x @ W_gate  [16384,1536]
    sgemm_kernel<<<dim3(OUT_CPLX/BN, NTOK/BM, 1), 256>>>(
        NTOK, OUT_CPLX, PD, x, PD, 0, W_gate, OUT_CPLX, 0, p_gate, OUT_CPLX, 0);

    // 6) epilogue: out_flat + gated rmsnorm -> out_n
    epilogue1_kernel<<<NTOK, 256>>>(gnw);

    // 7) batched readout: yraw[:,k,:] = out_n[:,k,:] @ W_read[k]  (12 batches)
    sgemm_kernel<<<dim3(384/BN + 1, NTOK/BM, PK), 256>>>(
        NTOK, 384, 2*PH,
        p_outn, OUT_CPLX, (long long)(2*PH),
        W_read, 384, (long long)(2*PH)*384,
        p_yraw, PK*384, (long long)384);

    // 8) gating -> y [16384,2304]
    ygate_kernel<<<dim3((PK*DIM_EXPAND+255)/256, NTOK), 256>>>();

    // 9) final: out = y @ W_out  [16384,768]
    sgemm_kernel<<<dim3(PD/BN, NTOK/BM, 1), 256>>>(
        NTOK, PD, PK*DIM_EXPAND, p_y, PK*DIM_EXPAND, 0, W_out, PD, 0, out, PD, 0);
}

// round 2
// speedup vs baseline: 1.0048x; 1.0048x over previous
#include <cuda_runtime.h>
#include <cuda_bf16.h>
#include <math.h>

// ---------------- problem constants ----------------
#define PK      12          // K
#define PKQ     6           // K_Q
#define PH      64          // H
#define PD      768         // D
#define DIM_MEM 768         // K*H
#define DIM_MEM_TOT 780     // +K
#define DIM_CONV 1548
#define OUT_CPLX 1536
#define DIM_EXPAND 192
#define PMAXLEN 4096
#define PKSIZE  4
#define PB      4
#define PL      4096
#define NTOK    (PB*PL)     // 16384
#define NCHUNK  8
#define CHROWS  (PL/NCHUNK) // 512

// ---------------- device scratch -------------------
__device__ float g_buf0[(size_t)NTOK*DIM_CONV];   // z_pre, then stack/cumsum
__device__ float g_z   [(size_t)NTOK*DIM_CONV];   // conv+silu output
__device__ float g_outn[(size_t)NTOK*OUT_CPLX];   // normalized out
__device__ float g_gate[(size_t)NTOK*OUT_CPLX];   // x @ W_gate
__device__ float g_yraw[(size_t)NTOK*(PK*384)];   // readout raw
__device__ float g_y   [(size_t)NTOK*(PK*DIM_EXPAND)]; // gated readout
__device__ float g_csum[(size_t)PB*NCHUNK*DIM_CONV];   // chunk sums -> offsets
__device__ float g_theta[PK*PH];
__device__ float g_wint [PK*PH];
__device__ float g_slope[PK];

// ---------------- helpers --------------------------
__device__ __forceinline__ float sigmoidf_(float x){ return 1.f/(1.f+expf(-x)); }
__device__ __forceinline__ float softplusf_(float x){ return (x>20.f)? x : log1pf(expf(x)); }

// ---------------- small precompute ------------------
__global__ void prep_kernel(const float* __restrict__ theta_raw,
                            const float* __restrict__ wint_raw,
                            const float* __restrict__ decay)
{
    int i = threadIdx.x;
    if (i < PK*PH) {
        g_theta[i] = 0.001f + 2.999f * sigmoidf_(theta_raw[i]);
        float e = expf(wint_raw[i]);
        g_wint[i] = e / (e + 1e-6f);
    }
    if (i < PK) g_slope[i] = softplusf_(decay[i]);
}

// ---------------- generic batched SGEMM -------------
// C[M,N] = A[M,K] * B[K,N], row-major, fp32. M%128==0, K%16==0, N%4==0.
// Inner product uses packed f32x2 FMA (FFMA2) for 2x fp32 pipe throughput.
#define BM 128
#define BN 128
#define BKD 16
#define TM 8
#define TN 8

__global__ void __launch_bounds__(256, 2)
sgemm_kernel(int M, int N, int Kd,
             const float* __restrict__ A, int lda, long long sA,
             const float* __restrict__ B, int ldb, long long sB,
             float* __restrict__ C, int ldc, long long sC)
{
    __shared__ float As[BKD][BM+4];
    __shared__ __align__(16) float Bs[BKD][BN];

    int zb = blockIdx.z;
    A += (long long)zb * sA;
    B += (long long)zb * sB;
    C += (long long)zb * sC;

    const int tile_n = blockIdx.x * BN;
    const int tile_m = blockIdx.y * BM;
    const int tid = threadIdx.x;
    const int tx = tid & 15;
    const int ty = tid >> 4;

    // packed accumulators: acc2[i][j2] holds columns (2*j2, 2*j2+1)
    unsigned long long acc2[TM][TN/2];
#pragma unroll
    for (int i = 0; i < TM; i++)
#pragma unroll
        for (int j = 0; j < TN/2; j++) acc2[i][j] = 0ULL;

    for (int k0 = 0; k0 < Kd; k0 += BKD) {
        // A tile -> transposed smem
#pragma unroll
        for (int i = 0; i < 2; i++) {
            int lin = tid + i*256;
            int row = lin >> 2;
            int kq  = (lin & 3) << 2;
            const float4 v = *(const float4*)(A + (long long)(tile_m + row)*lda + k0 + kq);
            As[kq+0][row] = v.x;
            As[kq+1][row] = v.y;
            As[kq+2][row] = v.z;
            As[kq+3][row] = v.w;
        }
        // B tile
#pragma unroll
        for (int i = 0; i < 2; i++) {
            int lin = tid + i*256;
            int kr = lin >> 5;
            int c4 = (lin & 31) << 2;
            int gcol = tile_n + c4;
            float4 v = make_float4(0.f,0.f,0.f,0.f);
            if (gcol < N)
                v = *(const float4*)(B + (long long)(k0+kr)*ldb + gcol);
            *(float4*)&Bs[kr][c4] = v;
        }
        __syncthreads();

#pragma unroll
        for (int kk = 0; kk < BKD; kk++) {
            // load B as packed 64-bit pairs (8B-aligned: tx*TN stride = 32B)
            unsigned long long bD[TN/2];
#pragma unroll
            for (int j2 = 0; j2 < TN/2; j2++)
                bD[j2] = *(const unsigned long long*)&Bs[kk][tx*TN + 2*j2];
            // load + duplicate A into packed pairs
            unsigned long long aD[TM];
#pragma unroll
            for (int i = 0; i < TM; i++) {
                unsigned int au = __float_as_uint(As[kk][ty*TM + i]);
                asm("mov.b64 %0, {%1, %1};" : "=l"(aD[i]) : "r"(au));
            }
#pragma unroll
            for (int i = 0; i < TM; i++)
#pragma unroll
                for (int j2 = 0; j2 < TN/2; j2++)
                    asm("fma.rn.f32x2 %0, %1, %2, %0;"
                        : "+l"(acc2[i][j2]) : "l"(aD[i]), "l"(bD[j2]));
        }
        __syncthreads();
    }

#pragma unroll
    for (int i = 0; i < TM; i++) {
        long long row = tile_m + ty*TM + i;
        float* Crow = C + row*(long long)ldc;
#pragma unroll
        for (int j4 = 0; j4 < TN; j4 += 4) {
            int col = tile_n + tx*TN + j4;
            if (col < N) {
                unsigned int l0, h0, l1, h1;
                asm("mov.b64 {%0, %1}, %2;" : "=r"(l0), "=r"(h0) : "l"(acc2[i][j4/2]));
                asm("mov.b64 {%0, %1}, %2;" : "=r"(l1), "=r"(h1) : "l"(acc2[i][j4/2+1]));
                *(float4*)(Crow + col) = make_float4(__uint_as_float(l0), __uint_as_float(h0),
                                                     __uint_as_float(l1), __uint_as_float(h1));
            }
        }
    }
}

// ---------------- causal depthwise conv + silu ------
__global__ void conv_silu_kernel(const float* __restrict__ conv_w)
{
    int c = blockIdx.x * blockDim.x + threadIdx.x;
    if (c >= DIM_CONV) return;
    int tok = blockIdx.y;
    int l = tok & (PL-1);

    long long base = (long long)tok * DIM_CONV + c;
    float acc = 0.f;
#pragma unroll
    for (int t = 0; t < PKSIZE; t++) {
        int dl = l + t - (PKSIZE-1);
        if (dl >= 0)
            acc += g_buf0[base + (long long)(t - (PKSIZE-1)) * DIM_CONV] * conv_w[t*DIM_CONV + c];
    }
    g_z[base] = acc * sigmoidf_(acc);
}

// ---------------- stack builder ---------------------
// stack[tok] = [p_w(12), re(768), im(768)]
__global__ void stack_kernel(const float* __restrict__ score_scale,
                             const float* __restrict__ score_bias,
                             const float* __restrict__ phase_scale)
{
    __shared__ float s_pw[PK];
    int tok = blockIdx.x;
    int tid = threadIdx.x;
    int l = tok & (PL-1);
    long long zb = (long long)tok * DIM_CONV;

    if (tid < PK) {
        float s  = g_z[zb + DIM_MEM + tid];
        float u  = score_scale[tid]*s + score_bias[tid];
        float sp = softplusf_(u);
        float tw = expf(-g_slope[tid] * (float)(PMAXLEN-1 - l));
        float p  = fminf(fmaxf(sp*tw, 1e-4f), 5000.f);
        s_pw[tid] = p;
        g_buf0[zb + tid] = p;
    }
    __syncthreads();

    for (int i = tid; i < DIM_MEM; i += blockDim.x) {
        int k = i >> 6;
        float kv = g_z[zb + i];
        float ks = kv * phase_scale[k];
        float phi = ks / (1.f + fabsf(ks)) * g_theta[i];
        float sn, cs;
        sincosf(phi, &sn, &cs);
        float kvw = kv * s_pw[k];
        g_buf0[zb + PK + i]           = kvw * cs;
        g_buf0[zb + PK + DIM_MEM + i] = kvw * sn;
    }
}

// ---------------- chunked scan ----------------------
__global__ void scan_partial_kernel()
{
    int c = blockIdx.x * blockDim.x + threadIdx.x;
    if (c >= DIM_CONV) return;
    int chunk = blockIdx.y;
    int b = blockIdx.z;

    long long base = ((long long)(b*PL + chunk*CHROWS)) * DIM_CONV + c;
    float run = 0.f;
#pragma unroll 4
    for (int r = 0; r < CHROWS; r++) {
        long long p = base + (long long)r * DIM_CONV;
        run += g_buf0[p];
        g_buf0[p] = run;
    }
    g_csum[((long long)(b*NCHUNK + chunk))*DIM_CONV + c] = run;
}

__global__ void scan_offsets_kernel()
{
    int i = blockIdx.x * blockDim.x + threadIdx.x;
    if (i >= PB*DIM_CONV) return;
    int b = i / DIM_CONV;
    int c = i - b*DIM_CONV;
    float off = 0.f;
#pragma unroll
    for (int ch = 0; ch < NCHUNK; ch++) {
        long long idx = ((long long)(b*NCHUNK + ch))*DIM_CONV + c;
        float t = g_csum[idx];
        g_csum[idx] = off;      // exclusive prefix
        off += t;
    }
}

// ---------------- epilogue 1: out_flat + gated rmsnorm
__global__ void epilogue1_kernel(const float* __restrict__ gnw)
{
    __shared__ float s_inv[PK];
    __shared__ float s_red[8];
    int tok = blockIdx.x;
    int tid = threadIdx.x;
    int l = tok & (PL-1);
    int b = tok >> 12;
    int chunk = l >> 9;  // l / 512

    long long zb  = (long long)tok * DIM_CONV;
    long long ob  = ((long long)(b*NCHUNK + chunk)) * DIM_CONV;
    long long gb  = (long long)tok * OUT_CPLX;

    if (tid < PK) {
        float den = g_buf0[zb + tid] + g_csum[ob + tid];
        s_inv[tid] = 1.f / fmaxf(den, 1e-4f);
    }
    __syncthreads();

    float hvals[OUT_CPLX/256];
    float sumsq = 0.f;
#pragma unroll
    for (int it = 0; it < OUT_CPLX/256; it++) {
        int f = tid + it*256;
        int k = f >> 7;
        int j = f & 127;
        int h = j & 63;
        int is_im = j >> 6;
        int idx = k*PH + h;

        float re_acc = g_buf0[zb + PK + idx]           + g_csum[ob + PK + idx];
        float im_acc = g_buf0[zb + PK + DIM_MEM + idx] + g_csum[ob + PK + DIM_MEM + idx];
        float sre = re_acc * s_inv[k];
        float sim = im_acc * s_inv[k];
        int kq = k >> 1;
        float qre = g_z[zb + DIM_MEM_TOT + (kq*PH + h)*2];
        float qim = g_z[zb + DIM_MEM_TOT + (kq*PH + h)*2 + 1];
        float val;
        if (!is_im) val = (sre*qre + sim*qim);
        else        val = (sim*qre - sre*qim);
        val *= 0.125f * g_wint[idx];   // H^-0.5 = 1/8

        float gv = g_gate[gb + f];
        float hv = val * (gv * sigmoidf_(gv));
        hvals[it] = hv;
        sumsq += hv*hv;
    }
    // block reduction
#pragma unroll
    for (int o = 16; o > 0; o >>= 1) sumsq += __shfl_xor_sync(0xffffffff, sumsq, o);
    if ((tid & 31) == 0) s_red[tid >> 5] = sumsq;
    __syncthreads();
    if (tid < 32) {
        float v = (tid < 8) ? s_red[tid] : 0.f;
#pragma unroll
        for (int o = 4; o > 0; o >>= 1) v += __shfl_xor_sync(0xffffffff, v, o);
        if (tid == 0) s_red[0] = v;
    }
    __syncthreads();
    float rms = rsqrtf(s_red[0] / (float)OUT_CPLX + 1e-6f);

#pragma unroll
    for (int it = 0; it < OUT_CPLX/256; it++) {
        int f = tid + it*256;
        g_outn[gb + f] = hvals[it] * rms * gnw[f];
    }
}

// ---------------- readout gating --------------------
__global__ void ygate_kernel()
{
    int j = blockIdx.x * blockDim.x + threadIdx.x;
    if (j >= PK*DIM_EXPAND) return;
    int tok = blockIdx.y;
    int k = j / DIM_EXPAND;
    int n = j - k*DIM_EXPAND;
    long long yb = (long long)tok * (PK*384);
    float v = g_yraw[yb + k*384 + n];
    float g = g_yraw[yb + k*384 + DIM_EXPAND + n];
    g_y[(long long)tok*(PK*DIM_EXPAND) + j] = v * sigmoidf_(g);
}

// ---------------- launcher --------------------------
extern "C" void kernel_launch(void* const* d_in, const int* in_sizes, int n_in,
                              void* d_out, int out_size)
{
    const float* x        = (const float*)d_in[0];
    const float* W_in     = (const float*)d_in[1];
    const float* conv_w   = (const float*)d_in[2];
    const float* theta_raw= (const float*)d_in[3];
    const float* wint_raw = (const float*)d_in[4];
    const float* decay    = (const float*)d_in[5];
    const float* sscale   = (const float*)d_in[6];
    const float* sbias    = (const float*)d_in[7];
    const float* pscale   = (const float*)d_in[8];
    const float* gnw      = (const float*)d_in[9];
    const float* W_read   = (const float*)d_in[10];
    const float* W_gate   = (const float*)d_in[11];
    const float* W_out    = (const float*)d_in[12];
    float* out            = (float*)d_out;

    float *p_buf0, *p_z, *p_outn, *p_gate, *p_yraw, *p_y;
    cudaGetSymbolAddress((void**)&p_buf0, g_buf0);
    cudaGetSymbolAddress((void**)&p_z,    g_z);
    cudaGetSymbolAddress((void**)&p_outn, g_outn);
    cudaGetSymbolAddress((void**)&p_gate, g_gate);
    cudaGetSymbolAddress((void**)&p_yraw, g_yraw);
    cudaGetSymbolAddress((void**)&p_y,    g_y);

    // 0) tiny precompute
    prep_kernel<<<1, 768>>>(theta_raw, wint_raw, decay);

    // 1) z_pre = x @ W_in   [16384,1548]
    sgemm_kernel<<<dim3((DIM_CONV+BN-1)/BN, NTOK/BM, 1), 256>>>(
        NTOK, DIM_CONV, PD, x, PD, 0, W_in, DIM_CONV, 0, p_buf0, DIM_CONV, 0);

    // 2) conv + silu -> z
    conv_silu_kernel<<<dim3((DIM_CONV+255)/256, NTOK), 256>>>(conv_w);

    // 3) build stack (overwrites g_buf0)
    stack_kernel<<<NTOK, 256>>>(sscale, sbias, pscale);

    // 4) chunked cumsum over L (in-place, offsets kept separate)
    scan_partial_kernel<<<dim3((DIM_CONV+127)/128, NCHUNK, PB), 128>>>();
    scan_offsets_kernel<<<(PB*DIM_CONV+255)/256, 256>>>();

    // 5) gate = x @ W_gate  [16384,1536]
    sgemm_kernel<<<dim3(OUT_CPLX/BN, NTOK/BM, 1), 256>>>(
        NTOK, OUT_CPLX, PD, x, PD, 0, W_gate, OUT_CPLX, 0, p_gate, OUT_CPLX, 0);

    // 6) epilogue: out_flat + gated rmsnorm -> out_n
    epilogue1_kernel<<<NTOK, 256>>>(gnw);

    // 7) batched readout: yraw[:,k,:] = out_n[:,k,:] @ W_read[k]  (12 batches)
    sgemm_kernel<<<dim3(384/BN + 1, NTOK/BM, PK), 256>>>(
        NTOK, 384, 2*PH,
        p_outn, OUT_CPLX, (long long)(2*PH),
        W_read, 384, (long long)(2*PH)*384,
        p_yraw, PK*384, (long long)384);

    // 8) gating -> y [16384,2304]
    ygate_kernel<<<dim3((PK*DIM_EXPAND+255)/256, NTOK), 256>>>();

    // 9) final: out = y @ W_out  [16384,768]
    sgemm_kernel<<<dim3(PD/BN, NTOK/BM, 1), 256>>>(
        NTOK, PD, PK*DIM_EXPAND, p_y, PK*DIM_EXPAND, 0, W_out, PD, 0, out, PD, 0);
}

// round 5
// speedup vs baseline: 1.8194x; 1.8106x over previous
#include <cuda_runtime.h>
#include <cuda_bf16.h>
#include <math.h>
#include <stdint.h>

// ---------------- problem constants ----------------
#define PK      12
#define PKQ     6
#define PH      64
#define PD      768
#define DIM_MEM 768
#define DIM_MEM_TOT 780
#define DIM_CONV 1548
#define OUT_CPLX 1536
#define DIM_EXPAND 192
#define PMAXLEN 4096
#define PKSIZE  4
#define PB      4
#define PL      4096
#define NTOK    (PB*PL)
#define NCHUNK  8
#define CHROWS  (PL/NCHUNK)

// ---------------- device scratch -------------------
__device__ float g_buf0[(size_t)NTOK*DIM_CONV];
__device__ float g_z   [(size_t)NTOK*DIM_CONV];
__device__ float g_gate[(size_t)NTOK*OUT_CPLX];
__device__ float g_yraw[(size_t)NTOK*(PK*384)];
__device__ float g_csum[(size_t)PB*NCHUNK*DIM_CONV];
__device__ float g_theta[PK*PH];
__device__ float g_wint [PK*PH];
__device__ float g_slope[PK];

// bf16 split operands
__device__ __nv_bfloat16 g_xh[(size_t)NTOK*PD];
__device__ __nv_bfloat16 g_xl[(size_t)NTOK*PD];
__device__ __nv_bfloat16 g_Winh[(size_t)DIM_CONV*PD];
__device__ __nv_bfloat16 g_Winl[(size_t)DIM_CONV*PD];
__device__ __nv_bfloat16 g_Wgh[(size_t)OUT_CPLX*PD];
__device__ __nv_bfloat16 g_Wgl[(size_t)OUT_CPLX*PD];
__device__ __nv_bfloat16 g_Woh[(size_t)PD*(PK*DIM_EXPAND)];
__device__ __nv_bfloat16 g_Wol[(size_t)PD*(PK*DIM_EXPAND)];
__device__ __nv_bfloat16 g_Wrh[(size_t)PK*384*128];
__device__ __nv_bfloat16 g_Wrl[(size_t)PK*384*128];
__device__ __nv_bfloat16 g_onh[(size_t)NTOK*OUT_CPLX];
__device__ __nv_bfloat16 g_onl[(size_t)NTOK*OUT_CPLX];
__device__ __nv_bfloat16 g_yh[(size_t)NTOK*(PK*DIM_EXPAND)];
__device__ __nv_bfloat16 g_yl[(size_t)NTOK*(PK*DIM_EXPAND)];

// ---------------- helpers --------------------------
__device__ __forceinline__ float sigmoidf_(float x){ return 1.f/(1.f+expf(-x)); }
__device__ __forceinline__ float softplusf_(float x){ return (x>20.f)? x : log1pf(expf(x)); }
__device__ __forceinline__ void split2(float v, __nv_bfloat16& h, __nv_bfloat16& l){
    h = __float2bfloat16(v);
    l = __float2bfloat16(v - __bfloat162float(h));
}
__device__ __forceinline__ uint32_t smem_u32(const void* p){
    uint32_t a;
    asm("{ .reg .u64 t; cvta.to.shared.u64 t, %1; cvt.u32.u64 %0, t; }" : "=r"(a) : "l"(p));
    return a;
}
__device__ __forceinline__ void cp16(uint32_t dst, const void* src){
    asm volatile("cp.async.ca.shared.global [%0], [%1], 16;" :: "r"(dst), "l"(src));
}
template<int NG> __device__ __forceinline__ void cpwait(){
    asm volatile("cp.async.wait_group %0;" :: "n"(NG) : "memory");
}
__device__ __forceinline__ void cpcommit(){
    asm volatile("cp.async.commit_group;" ::: "memory");
}
__device__ __forceinline__ void mma16816(float* c, uint32_t a0, uint32_t a1, uint32_t a2, uint32_t a3,
                                         uint32_t b0, uint32_t b1){
    asm volatile(
        "mma.sync.aligned.m16n8k16.row.col.f32.bf16.bf16.f32 "
        "{%0,%1,%2,%3}, {%4,%5,%6,%7}, {%8,%9}, {%0,%1,%2,%3};"
        : "+f"(c[0]), "+f"(c[1]), "+f"(c[2]), "+f"(c[3])
        : "r"(a0), "r"(a1), "r"(a2), "r"(a3), "r"(b0), "r"(b1));
}

// ---------------- split-bf16 HMMA GEMM --------------
// C[M,N] = (Ah+Al)[M,K] * (Bh+Bl)[N,K]^T  (B rows are K-major)
// 3 passes accumulated in fp32 register fragments.
#define GBM 128
#define GBN 128
#define GBK 32
#define SA  40                      // padded row stride (elems)
#define TILE_ELEMS (128*SA)         // 5120
#define TILE_BYTES (TILE_ELEMS*2)   // 10240
#define STAGE_BYTES (4*TILE_BYTES)  // 40960
#define GSMEM (2*STAGE_BYTES)       // 81920

__global__ void __launch_bounds__(256, 1)
gemm_mma_kernel(int M, int N, int Kd,
                const __nv_bfloat16* __restrict__ Ah, const __nv_bfloat16* __restrict__ Al,
                long long lda, long long sAb,
                const __nv_bfloat16* __restrict__ Bh, const __nv_bfloat16* __restrict__ Bl,
                long long ldb, long long sBb,
                float* __restrict__ C, long long ldc, long long sCb)
{
    extern __shared__ char smem[];
    const uint32_t smb = smem_u32(smem);
    const int tid = threadIdx.x;
    const int wid = tid >> 5;
    const int lid = tid & 31;
    const int g = lid >> 2;
    const int t = lid & 3;
    const int wm = (wid & 1) * 64;   // warp m offset
    const int wn = (wid >> 1) * 32;  // warp n offset

    const int zb = blockIdx.z;
    Ah += (long long)zb * sAb;  Al += (long long)zb * sAb;
    Bh += (long long)zb * sBb;  Bl += (long long)zb * sBb;
    C  += (long long)zb * sCb;

    const int tile_n = blockIdx.x * GBN;
    const int tile_m = blockIdx.y * GBM;
    const int nChunks = Kd / GBK;

    float acc[4][4][4];
#pragma unroll
    for (int i = 0; i < 4; i++)
#pragma unroll
        for (int j = 0; j < 4; j++)
#pragma unroll
            for (int r = 0; r < 4; r++) acc[i][j][r] = 0.f;

    // ---- stage loader: 2048 16B chunks, 8 per thread ----
    auto load_stage = [&](int stage, int k0){
        uint32_t sbase = smb + stage * STAGE_BYTES;
#pragma unroll
        for (int it = 0; it < 8; it++) {
            int idx = tid + it * 256;
            int tile = idx >> 9;          // 0:Ah 1:Al 2:Bh 3:Bl
            int r    = (idx >> 2) & 127;
            int seg  = idx & 3;
            uint32_t dst = sbase + tile * TILE_BYTES + r * (SA*2) + seg * 16;
            const __nv_bfloat16* src;
            if (tile == 0)      src = Ah + (long long)(tile_m + r) * lda + k0 + seg*8;
            else if (tile == 1) src = Al + (long long)(tile_m + r) * lda + k0 + seg*8;
            else {
                int n = tile_n + r;
                if (n >= N) n = 0;        // clamp (cols >= N never stored)
                src = (tile == 2 ? Bh : Bl) + (long long)n * ldb + k0 + seg*8;
            }
            cp16(dst, src);
        }
        cpcommit();
    };

    // ---- compute one K-chunk from a stage ----
    auto compute = [&](int stage){
        const __nv_bfloat16* S = (const __nv_bfloat16*)(smem + stage * STAGE_BYTES);
        const __nv_bfloat16* As_h = S;
        const __nv_bfloat16* As_l = S + TILE_ELEMS;
        const __nv_bfloat16* Bs_h = S + 2*TILE_ELEMS;
        const __nv_bfloat16* Bs_l = S + 3*TILE_ELEMS;
#pragma unroll
        for (int ks = 0; ks < GBK; ks += 16) {
            uint32_t bh0[4], bh1[4], bl0[4], bl1[4];
#pragma unroll
            for (int nt = 0; nt < 4; nt++) {
                int off = (wn + nt*8 + g) * SA + ks + 2*t;
                bh0[nt] = *(const uint32_t*)(Bs_h + off);
                bh1[nt] = *(const uint32_t*)(Bs_h + off + 8);
                bl0[nt] = *(const uint32_t*)(Bs_l + off);
                bl1[nt] = *(const uint32_t*)(Bs_l + off + 8);
            }
#pragma unroll
            for (int mt = 0; mt < 4; mt++) {
                int off = (wm + mt*16 + g) * SA + ks + 2*t;
                uint32_t ah0 = *(const uint32_t*)(As_h + off);
                uint32_t ah1 = *(const uint32_t*)(As_h + off + 8*SA);
                uint32_t ah2 = *(const uint32_t*)(As_h + off + 8);
                uint32_t ah3 = *(const uint32_t*)(As_h + off + 8*SA + 8);
                uint32_t al0 = *(const uint32_t*)(As_l + off);
                uint32_t al1 = *(const uint32_t*)(As_l + off + 8*SA);
                uint32_t al2 = *(const uint32_t*)(As_l + off + 8);
                uint32_t al3 = *(const uint32_t*)(As_l + off + 8*SA + 8);
#pragma unroll
                for (int nt = 0; nt < 4; nt++)
                    mma16816(acc[mt][nt], ah0, ah1, ah2, ah3, bh0[nt], bh1[nt]);
#pragma unroll
                for (int nt = 0; nt < 4; nt++)
                    mma16816(acc[mt][nt], al0, al1, al2, al3, bh0[nt], bh1[nt]);
#pragma unroll
                for (int nt = 0; nt < 4; nt++)
                    mma16816(acc[mt][nt], ah0, ah1, ah2, ah3, bl0[nt], bl1[nt]);
            }
        }
    };

    load_stage(0, 0);
    for (int i = 0; i < nChunks; i++) {
        if (i + 1 < nChunks) {
            load_stage((i + 1) & 1, (i + 1) * GBK);
            cpwait<1>();
        } else {
            cpwait<0>();
        }
        __syncthreads();
        compute(i & 1);
        __syncthreads();
    }

    // ---- store ----
#pragma unroll
    for (int mt = 0; mt < 4; mt++) {
        int row0 = tile_m + wm + mt*16 + g;
#pragma unroll
        for (int nt = 0; nt < 4; nt++) {
            int col = tile_n + wn + nt*8 + 2*t;
            if (col < N) {
                float* p0 = C + (long long)row0 * ldc + col;
                float* p1 = C + (long long)(row0 + 8) * ldc + col;
                p0[0] = acc[mt][nt][0]; p0[1] = acc[mt][nt][1];
                p1[0] = acc[mt][nt][2]; p1[1] = acc[mt][nt][3];
            }
        }
    }
}

// ---------------- conversion kernels ----------------
__global__ void split_x_kernel(const float* __restrict__ x)
{
    size_t i = (size_t)blockIdx.x * blockDim.x + threadIdx.x;
    if (i >= (size_t)NTOK * PD) return;
    split2(x[i], g_xh[i], g_xl[i]);
}

// W[K,N] row-major -> out[N,K] (hi/lo)
__global__ void tsplit_kernel(const float* __restrict__ W,
                              __nv_bfloat16* __restrict__ oh,
                              __nv_bfloat16* __restrict__ ol,
                              int K, int N)
{
    int i = blockIdx.x * blockDim.x + threadIdx.x;
    if (i >= K * N) return;
    int k = i / N, n = i - k * N;
    __nv_bfloat16 h, l;
    split2(W[i], h, l);
    oh[(size_t)n * K + k] = h;
    ol[(size_t)n * K + k] = l;
}

// W_read[12][128][384] -> [12][384][128]
__global__ void tsplit_wr_kernel(const float* __restrict__ W)
{
    int i = blockIdx.x * blockDim.x + threadIdx.x;
    if (i >= PK * 128 * 384) return;
    int b = i / (128 * 384);
    int rem = i - b * 128 * 384;
    int r = rem / 384, c = rem - r * 384;
    __nv_bfloat16 h, l;
    split2(W[i], h, l);
    size_t o = (size_t)b * 384 * 128 + (size_t)c * 128 + r;
    g_Wrh[o] = h; g_Wrl[o] = l;
}

// ---------------- small precompute ------------------
__global__ void prep_kernel(const float* __restrict__ theta_raw,
                            const float* __restrict__ wint_raw,
                            const float* __restrict__ decay)
{
    int i = threadIdx.x;
    if (i < PK*PH) {
        g_theta[i] = 0.001f + 2.999f * sigmoidf_(theta_raw[i]);
        float e = expf(wint_raw[i]);
        g_wint[i] = e / (e + 1e-6f);
    }
    if (i < PK) g_slope[i] = softplusf_(decay[i]);
}

// ---------------- causal depthwise conv + silu ------
__global__ void conv_silu_kernel(const float* __restrict__ conv_w)
{
    int c = blockIdx.x * blockDim.x + threadIdx.x;
    if (c >= DIM_CONV) return;
    int tok = blockIdx.y;
    int l = tok & (PL-1);

    long long base = (long long)tok * DIM_CONV + c;
    float acc = 0.f;
#pragma unroll
    for (int t = 0; t < PKSIZE; t++) {
        int dl = l + t - (PKSIZE-1);
        if (dl >= 0)
            acc += g_buf0[base + (long long)(t - (PKSIZE-1)) * DIM_CONV] * conv_w[t*DIM_CONV + c];
    }
    g_z[base] = acc * sigmoidf_(acc);
}

// ---------------- stack builder ---------------------
__global__ void stack_kernel(const float* __restrict__ score_scale,
                             const float* __restrict__ score_bias,
                             const float* __restrict__ phase_scale)
{
    __shared__ float s_pw[PK];
    int tok = blockIdx.x;
    int tid = threadIdx.x;
    int l = tok & (PL-1);
    long long zb = (long long)tok * DIM_CONV;

    if (tid < PK) {
        float s  = g_z[zb + DIM_MEM + tid];
        float u  = score_scale[tid]*s + score_bias[tid];
        float sp = softplusf_(u);
        float tw = expf(-g_slope[tid] * (float)(PMAXLEN-1 - l));
        float p  = fminf(fmaxf(sp*tw, 1e-4f), 5000.f);
        s_pw[tid] = p;
        g_buf0[zb + tid] = p;
    }
    __syncthreads();

    for (int i = tid; i < DIM_MEM; i += blockDim.x) {
        int k = i >> 6;
        float kv = g_z[zb + i];
        float ks = kv * phase_scale[k];
        float phi = ks / (1.f + fabsf(ks)) * g_theta[i];
        float sn, cs;
        sincosf(phi, &sn, &cs);
        float kvw = kv * s_pw[k];
        g_buf0[zb + PK + i]           = kvw * cs;
        g_buf0[zb + PK + DIM_MEM + i] = kvw * sn;
    }
}

// ---------------- chunked scan ----------------------
__global__ void scan_partial_kernel()
{
    int c = blockIdx.x * blockDim.x + threadIdx.x;
    if (c >= DIM_CONV) return;
    int chunk = blockIdx.y;
    int b = blockIdx.z;

    long long base = ((long long)(b*PL + chunk*CHROWS)) * DIM_CONV + c;
    float run = 0.f;
#pragma unroll 4
    for (int r = 0; r < CHROWS; r++) {
        long long p = base + (long long)r * DIM_CONV;
        run += g_buf0[p];
        g_buf0[p] = run;
    }
    g_csum[((long long)(b*NCHUNK + chunk))*DIM_CONV + c] = run;
}

__global__ void scan_offsets_kernel()
{
    int i = blockIdx.x * blockDim.x + threadIdx.x;
    if (i >= PB*DIM_CONV) return;
    int b = i / DIM_CONV;
    int c = i - b*DIM_CONV;
    float off = 0.f;
#pragma unroll
    for (int ch = 0; ch < NCHUNK; ch++) {
        long long idx = ((long long)(b*NCHUNK + ch))*DIM_CONV + c;
        float t = g_csum[idx];
        g_csum[idx] = off;
        off += t;
    }
}

// ---------------- epilogue 1: out_flat + gated rmsnorm -> bf16 split
__global__ void epilogue1_kernel(const float* __restrict__ gnw)
{
    __shared__ float s_inv[PK];
    __shared__ float s_red[8];
    int tok = blockIdx.x;
    int tid = threadIdx.x;
    int l = tok & (PL-1);
    int b = tok >> 12;
    int chunk = l >> 9;

    long long zb  = (long long)tok * DIM_CONV;
    long long ob  = ((long long)(b*NCHUNK + chunk)) * DIM_CONV;
    long long gb  = (long long)tok * OUT_CPLX;

    if (tid < PK) {
        float den = g_buf0[zb + tid] + g_csum[ob + tid];
        s_inv[tid] = 1.f / fmaxf(den, 1e-4f);
    }
    __syncthreads();

    float hvals[OUT_CPLX/256];
    float sumsq = 0.f;
#pragma unroll
    for (int it = 0; it < OUT_CPLX/256; it++) {
        int f = tid + it*256;
        int k = f >> 7;
        int j = f & 127;
        int h = j & 63;
        int is_im = j >> 6;
        int idx = k*PH + h;

        float re_acc = g_buf0[zb + PK + idx]           + g_csum[ob + PK + idx];
        float im_acc = g_buf0[zb + PK + DIM_MEM + idx] + g_csum[ob + PK + DIM_MEM + idx];
        float sre = re_acc * s_inv[k];
        float sim = im_acc * s_inv[k];
        int kq = k >> 1;
        float qre = g_z[zb + DIM_MEM_TOT + (kq*PH + h)*2];
        float qim = g_z[zb + DIM_MEM_TOT + (kq*PH + h)*2 + 1];
        float val;
        if (!is_im) val = (sre*qre + sim*qim);
        else        val = (sim*qre - sre*qim);
        val *= 0.125f * g_wint[idx];

        float gv = g_gate[gb + f];
        float hv = val * (gv * sigmoidf_(gv));
        hvals[it] = hv;
        sumsq += hv*hv;
    }
#pragma unroll
    for (int o = 16; o > 0; o >>= 1) sumsq += __shfl_xor_sync(0xffffffff, sumsq, o);
    if ((tid & 31) == 0) s_red[tid >> 5] = sumsq;
    __syncthreads();
    if (tid < 32) {
        float v = (tid < 8) ? s_red[tid] : 0.f;
#pragma unroll
        for (int o = 4; o > 0; o >>= 1) v += __shfl_xor_sync(0xffffffff, v, o);
        if (tid == 0) s_red[0] = v;
    }
    __syncthreads();
    float rms = rsqrtf(s_red[0] / (float)OUT_CPLX + 1e-6f);

#pragma unroll
    for (int it = 0; it < OUT_CPLX/256; it++) {
        int f = tid + it*256;
        float v = hvals[it] * rms * gnw[f];
        __nv_bfloat16 h, lo;
        split2(v, h, lo);
        g_onh[gb + f] = h;
        g_onl[gb + f] = lo;
    }
}

// ---------------- readout gating -> bf16 split ------
__global__ void ygate_kernel()
{
    int j = blockIdx.x * blockDim.x + threadIdx.x;
    if (j >= PK*DIM_EXPAND) return;
    int tok = blockIdx.y;
    int k = j / DIM_EXPAND;
    int n = j - k*DIM_EXPAND;
    long long yb = (long long)tok * (PK*384);
    float v = g_yraw[yb + k*384 + n];
    float g = g_yraw[yb + k*384 + DIM_EXPAND + n];
    float r = v * sigmoidf_(g);
    __nv_bfloat16 h, l;
    split2(r, h, l);
    size_t o = (size_t)tok*(PK*DIM_EXPAND) + j;
    g_yh[o] = h;
    g_yl[o] = l;
}

// ---------------- launcher --------------------------
extern "C" void kernel_launch(void* const* d_in, const int* in_sizes, int n_in,
                              void* d_out, int out_size)
{
    const float* x        = (const float*)d_in[0];
    const float* W_in     = (const float*)d_in[1];
    const float* conv_w   = (const float*)d_in[2];
    const float* theta_raw= (const float*)d_in[3];
    const float* wint_raw = (const float*)d_in[4];
    const float* decay    = (const float*)d_in[5];
    const float* sscale   = (const float*)d_in[6];
    const float* sbias    = (const float*)d_in[7];
    const float* pscale   = (const float*)d_in[8];
    const float* gnw      = (const float*)d_in[9];
    const float* W_read   = (const float*)d_in[10];
    const float* W_gate   = (const float*)d_in[11];
    const float* W_out    = (const float*)d_in[12];
    float* out            = (float*)d_out;

    float *p_buf0, *p_gate, *p_yraw;
    __nv_bfloat16 *p_xh, *p_xl, *p_Winh, *p_Winl, *p_Wgh, *p_Wgl;
    __nv_bfloat16 *p_Woh, *p_Wol, *p_Wrh, *p_Wrl, *p_onh, *p_onl, *p_yh, *p_yl;
    cudaGetSymbolAddress((void**)&p_buf0, g_buf0);
    cudaGetSymbolAddress((void**)&p_gate, g_gate);
    cudaGetSymbolAddress((void**)&p_yraw, g_yraw);
    cudaGetSymbolAddress((void**)&p_xh,   g_xh);
    cudaGetSymbolAddress((void**)&p_xl,   g_xl);
    cudaGetSymbolAddress((void**)&p_Winh, g_Winh);
    cudaGetSymbolAddress((void**)&p_Winl, g_Winl);
    cudaGetSymbolAddress((void**)&p_Wgh,  g_Wgh);
    cudaGetSymbolAddress((void**)&p_Wgl,  g_Wgl);
    cudaGetSymbolAddress((void**)&p_Woh,  g_Woh);
    cudaGetSymbolAddress((void**)&p_Wol,  g_Wol);
    cudaGetSymbolAddress((void**)&p_Wrh,  g_Wrh);
    cudaGetSymbolAddress((void**)&p_Wrl,  g_Wrl);
    cudaGetSymbolAddress((void**)&p_onh,  g_onh);
    cudaGetSymbolAddress((void**)&p_onl,  g_onl);
    cudaGetSymbolAddress((void**)&p_yh,   g_yh);
    cudaGetSymbolAddress((void**)&p_yl,   g_yl);

    cudaFuncSetAttribute(gemm_mma_kernel,
                         cudaFuncAttributeMaxDynamicSharedMemorySize, GSMEM);

    // 0) precompute + conversions
    prep_kernel<<<1, 768>>>(theta_raw, wint_raw, decay);
    {
        size_t n = (size_t)NTOK * PD;
        split_x_kernel<<<(unsigned)((n + 255) / 256), 256>>>(x);
    }
    tsplit_kernel<<<(PD*DIM_CONV + 255)/256, 256>>>(W_in,  p_Winh, p_Winl, PD, DIM_CONV);
    tsplit_kernel<<<(PD*OUT_CPLX + 255)/256, 256>>>(W_gate, p_Wgh, p_Wgl, PD, OUT_CPLX);
    tsplit_kernel<<<(2304*PD + 255)/256, 256>>>(W_out, p_Woh, p_Wol, 2304, PD);
    tsplit_wr_kernel<<<(PK*128*384 + 255)/256, 256>>>(W_read);

    // 1) z_pre = x @ W_in   [16384,1548]
    gemm_mma_kernel<<<dim3((DIM_CONV + GBN - 1)/GBN, NTOK/GBM, 1), 256, GSMEM>>>(
        NTOK, DIM_CONV, PD, p_xh, p_xl, PD, 0, p_Winh, p_Winl, PD, 0, p_buf0, DIM_CONV, 0);

    // 2) conv + silu -> z
    conv_silu_kernel<<<dim3((DIM_CONV+255)/256, NTOK), 256>>>(conv_w);

    // 3) build stack
    stack_kernel<<<NTOK, 256>>>(sscale, sbias, pscale);

    // 4) chunked cumsum
    scan_partial_kernel<<<dim3((DIM_CONV+127)/128, NCHUNK, PB), 128>>>();
    scan_offsets_kernel<<<(PB*DIM_CONV+255)/256, 256>>>();

    // 5) gate = x @ W_gate  [16384,1536]
    gemm_mma_kernel<<<dim3(OUT_CPLX/GBN, NTOK/GBM, 1), 256, GSMEM>>>(
        NTOK, OUT_CPLX, PD, p_xh, p_xl, PD, 0, p_Wgh, p_Wgl, PD, 0, p_gate, OUT_CPLX, 0);

    // 6) epilogue: out_flat + gated rmsnorm -> bf16 split
    epilogue1_kernel<<<NTOK, 256>>>(gnw);

    // 7) batched readout (12 batches): [16384,384] = onh[:, k*128:+128] @ Wr[k]^T
    gemm_mma_kernel<<<dim3(384/GBN, NTOK/GBM, PK), 256, GSMEM>>>(
        NTOK, 384, 128,
        p_onh, p_onl, OUT_CPLX, 128,
        p_Wrh, p_Wrl, 128, (long long)384*128,
        p_yraw, PK*384, 384);

    // 8) gating -> bf16 split y
    ygate_kernel<<<dim3((PK*DIM_EXPAND+255)/256, NTOK), 256>>>();

    // 9) final: out = y @ W_out  [16384,768]
    gemm_mma_kernel<<<dim3(PD/GBN, NTOK/GBM, 1), 256, GSMEM>>>(
        NTOK, PD, PK*DIM_EXPAND, p_yh, p_yl, PK*DIM_EXPAND, 0,
        p_Woh, p_Wol, PK*DIM_EXPAND, 0, out, PD, 0);
}

// round 6
// speedup vs baseline: 1.9839x; 1.0905x over previous
#include <cuda_runtime.h>
#include <cuda_bf16.h>
#include <math.h>
#include <stdint.h>

// ---------------- problem constants ----------------
#define PK      12
#define PKQ     6
#define PH      64
#define PD      768
#define DIM_MEM 768
#define DIM_MEM_TOT 780
#define DIM_CONV 1548
#define OUT_CPLX 1536
#define DIM_EXPAND 192
#define PMAXLEN 4096
#define PKSIZE  4
#define PB      4
#define PL      4096
#define NTOK    (PB*PL)
#define NCHUNK  8
#define CHROWS  (PL/NCHUNK)

// ---------------- device scratch -------------------
__device__ float g_buf0[(size_t)NTOK*DIM_CONV];   // z_pre (GEMM1 out)
__device__ float g_z   [(size_t)NTOK*DIM_CONV];   // stack -> cumsum
__device__ float g_q   [(size_t)NTOK*768];        // q channels
__device__ float g_gate[(size_t)NTOK*OUT_CPLX];
__device__ float g_yraw[(size_t)NTOK*(PK*384)];
__device__ float g_csum[(size_t)PB*NCHUNK*DIM_CONV];
__device__ float g_theta[PK*PH];
__device__ float g_wint [PK*PH];
__device__ float g_slope[PK];

// bf16 split operands
__device__ __nv_bfloat16 g_xh[(size_t)NTOK*PD];
__device__ __nv_bfloat16 g_xl[(size_t)NTOK*PD];
__device__ __nv_bfloat16 g_Winh[(size_t)DIM_CONV*PD];
__device__ __nv_bfloat16 g_Winl[(size_t)DIM_CONV*PD];
__device__ __nv_bfloat16 g_Wgh[(size_t)OUT_CPLX*PD];
__device__ __nv_bfloat16 g_Wgl[(size_t)OUT_CPLX*PD];
__device__ __nv_bfloat16 g_Woh[(size_t)PD*(PK*DIM_EXPAND)];
__device__ __nv_bfloat16 g_Wol[(size_t)PD*(PK*DIM_EXPAND)];
__device__ __nv_bfloat16 g_Wrh[(size_t)PK*384*128];
__device__ __nv_bfloat16 g_Wrl[(size_t)PK*384*128];
__device__ __nv_bfloat16 g_onh[(size_t)NTOK*OUT_CPLX];
__device__ __nv_bfloat16 g_onl[(size_t)NTOK*OUT_CPLX];
__device__ __nv_bfloat16 g_yh[(size_t)NTOK*(PK*DIM_EXPAND)];
__device__ __nv_bfloat16 g_yl[(size_t)NTOK*(PK*DIM_EXPAND)];

// ---------------- helpers --------------------------
__device__ __forceinline__ float sigmoidf_(float x){ return 1.f/(1.f+expf(-x)); }
__device__ __forceinline__ float softplusf_(float x){ return (x>20.f)? x : log1pf(expf(x)); }
__device__ __forceinline__ void split2(float v, __nv_bfloat16& h, __nv_bfloat16& l){
    h = __float2bfloat16(v);
    l = __float2bfloat16(v - __bfloat162float(h));
}
__device__ __forceinline__ uint32_t smem_u32(const void* p){
    uint32_t a;
    asm("{ .reg .u64 t; cvta.to.shared.u64 t, %1; cvt.u32.u64 %0, t; }" : "=r"(a) : "l"(p));
    return a;
}
__device__ __forceinline__ void cp16(uint32_t dst, const void* src){
    asm volatile("cp.async.ca.shared.global [%0], [%1], 16;" :: "r"(dst), "l"(src));
}
template<int NG> __device__ __forceinline__ void cpwait(){
    asm volatile("cp.async.wait_group %0;" :: "n"(NG) : "memory");
}
__device__ __forceinline__ void cpcommit(){
    asm volatile("cp.async.commit_group;" ::: "memory");
}
__device__ __forceinline__ void mma16816(float* c, uint32_t a0, uint32_t a1, uint32_t a2, uint32_t a3,
                                         uint32_t b0, uint32_t b1){
    asm volatile(
        "mma.sync.aligned.m16n8k16.row.col.f32.bf16.bf16.f32 "
        "{%0,%1,%2,%3}, {%4,%5,%6,%7}, {%8,%9}, {%0,%1,%2,%3};"
        : "+f"(c[0]), "+f"(c[1]), "+f"(c[2]), "+f"(c[3])
        : "r"(a0), "r"(a1), "r"(a2), "r"(a3), "r"(b0), "r"(b1));
}
__device__ __forceinline__ void ldsm4(uint32_t& r0, uint32_t& r1, uint32_t& r2, uint32_t& r3, uint32_t addr){
    asm volatile("ldmatrix.sync.aligned.m8n8.x4.shared.b16 {%0,%1,%2,%3}, [%4];"
                 : "=r"(r0), "=r"(r1), "=r"(r2), "=r"(r3) : "r"(addr));
}

// ---------------- split-bf16 HMMA GEMM --------------
// C[M,N] = (Ah+Al)[M,K] * (Bh+Bl)[N,K]^T  (B rows K-major)
// 3 passes in fp32 fragments; ldmatrix fragment loads; 3-stage cp.async.
#define GBM 128
#define GBN 128
#define GBK 32
#define SA  40
#define TILE_ELEMS (128*SA)
#define TILE_BYTES (TILE_ELEMS*2)
#define STAGE_BYTES (4*TILE_BYTES)  // 40960
#define NSTAGE 3
#define GSMEM (NSTAGE*STAGE_BYTES)  // 122880

__global__ void __launch_bounds__(256, 1)
gemm_mma_kernel(int M, int N, int Kd,
                const __nv_bfloat16* __restrict__ Ah, const __nv_bfloat16* __restrict__ Al,
                long long lda, long long sAb,
                const __nv_bfloat16* __restrict__ Bh, const __nv_bfloat16* __restrict__ Bl,
                long long ldb, long long sBb,
                float* __restrict__ C, long long ldc, long long sCb)
{
    extern __shared__ char smem[];
    const uint32_t smb = smem_u32(smem);
    const int tid = threadIdx.x;
    const int wid = tid >> 5;
    const int lid = tid & 31;
    const int g = lid >> 2;
    const int t = lid & 3;
    const int wm = (wid & 1) * 64;
    const int wn = (wid >> 1) * 32;

    const int zb = blockIdx.z;
    Ah += (long long)zb * sAb;  Al += (long long)zb * sAb;
    Bh += (long long)zb * sBb;  Bl += (long long)zb * sBb;
    C  += (long long)zb * sCb;

    const int tile_n = blockIdx.x * GBN;
    const int tile_m = blockIdx.y * GBM;
    const int nChunks = Kd / GBK;

    // ldmatrix lane address components
    const int a_row  = (lid & 15);            // m row within 16
    const int a_koff = (lid >> 4) << 3;       // 0 or 8
    const int b_row  = (lid & 7) + ((lid >> 4) << 3);   // n row within 16
    const int b_koff = ((lid >> 3) & 1) << 3; // 0 or 8

    float acc[4][4][4];
#pragma unroll
    for (int i = 0; i < 4; i++)
#pragma unroll
        for (int j = 0; j < 4; j++)
#pragma unroll
            for (int r = 0; r < 4; r++) acc[i][j][r] = 0.f;

    auto load_stage = [&](int stage, int k0){
        uint32_t sbase = smb + stage * STAGE_BYTES;
#pragma unroll
        for (int it = 0; it < 8; it++) {
            int idx = tid + it * 256;
            int tile = idx >> 9;          // 0:Ah 1:Al 2:Bh 3:Bl
            int r    = (idx >> 2) & 127;
            int seg  = idx & 3;
            uint32_t dst = sbase + tile * TILE_BYTES + r * (SA*2) + seg * 16;
            const __nv_bfloat16* src;
            if (tile == 0)      src = Ah + (long long)(tile_m + r) * lda + k0 + seg*8;
            else if (tile == 1) src = Al + (long long)(tile_m + r) * lda + k0 + seg*8;
            else {
                int n = tile_n + r;
                if (n >= N) n = 0;
                src = (tile == 2 ? Bh : Bl) + (long long)n * ldb + k0 + seg*8;
            }
            cp16(dst, src);
        }
        cpcommit();
    };

    auto compute = [&](int stage){
        const uint32_t sb = smb + stage * STAGE_BYTES;
#pragma unroll
        for (int ks = 0; ks < GBK; ks += 16) {
            uint32_t bh[4][2], bl[4][2];
#pragma unroll
            for (int p = 0; p < 2; p++) {
                uint32_t addr = sb + 2*TILE_BYTES +
                    ((wn + p*16 + b_row) * SA + ks + b_koff) * 2;
                ldsm4(bh[2*p][0], bh[2*p][1], bh[2*p+1][0], bh[2*p+1][1], addr);
                addr += TILE_BYTES;
                ldsm4(bl[2*p][0], bl[2*p][1], bl[2*p+1][0], bl[2*p+1][1], addr);
            }
#pragma unroll
            for (int mt = 0; mt < 4; mt++) {
                uint32_t ah[4], al[4];
                uint32_t addr = sb + ((wm + mt*16 + a_row) * SA + ks + a_koff) * 2;
                ldsm4(ah[0], ah[1], ah[2], ah[3], addr);
                ldsm4(al[0], al[1], al[2], al[3], addr + TILE_BYTES);
#pragma unroll
                for (int nt = 0; nt < 4; nt++)
                    mma16816(acc[mt][nt], ah[0], ah[1], ah[2], ah[3], bh[nt][0], bh[nt][1]);
#pragma unroll
                for (int nt = 0; nt < 4; nt++)
                    mma16816(acc[mt][nt], al[0], al[1], al[2], al[3], bh[nt][0], bh[nt][1]);
#pragma unroll
                for (int nt = 0; nt < 4; nt++)
                    mma16816(acc[mt][nt], ah[0], ah[1], ah[2], ah[3], bl[nt][0], bl[nt][1]);
            }
        }
    };

    load_stage(0, 0);
    if (nChunks > 1) load_stage(1, GBK);
    for (int i = 0; i < nChunks; i++) {
        if (i == nChunks - 1) cpwait<0>(); else cpwait<1>();
        __syncthreads();
        if (i + 2 < nChunks) load_stage((i + 2) % NSTAGE, (i + 2) * GBK);
        compute(i % NSTAGE);
        __syncthreads();
    }

#pragma unroll
    for (int mt = 0; mt < 4; mt++) {
        int row0 = tile_m + wm + mt*16 + g;
#pragma unroll
        for (int nt = 0; nt < 4; nt++) {
            int col = tile_n + wn + nt*8 + 2*t;
            if (col < N) {
                float* p0 = C + (long long)row0 * ldc + col;
                float* p1 = C + (long long)(row0 + 8) * ldc + col;
                p0[0] = acc[mt][nt][0]; p0[1] = acc[mt][nt][1];
                p1[0] = acc[mt][nt][2]; p1[1] = acc[mt][nt][3];
            }
        }
    }
}

// ---------------- conversion kernels ----------------
__global__ void split_x_kernel(const float* __restrict__ x)
{
    size_t i = (size_t)blockIdx.x * blockDim.x + threadIdx.x;
    if (i >= (size_t)NTOK * PD) return;
    split2(x[i], g_xh[i], g_xl[i]);
}

// W[K,N] (batched) -> out[N,K] hi/lo via 32x32 smem tile transpose
__global__ void tsplit_kernel(const float* __restrict__ W,
                              __nv_bfloat16* __restrict__ oh,
                              __nv_bfloat16* __restrict__ ol,
                              int K, int N)
{
    __shared__ float tile[32][33];
    int zbk = blockIdx.z;
    size_t bs = (size_t)zbk * K * N;
    W += bs; oh += bs; ol += bs;
    int n0 = blockIdx.x * 32, k0 = blockIdx.y * 32;
    int tx = threadIdx.x, ty = threadIdx.y;
#pragma unroll
    for (int i = ty; i < 32; i += 8) {
        int n = n0 + tx;
        tile[i][tx] = (n < N) ? W[(size_t)(k0 + i) * N + n] : 0.f;
    }
    __syncthreads();
#pragma unroll
    for (int i = ty; i < 32; i += 8) {
        int n = n0 + i;
        if (n < N) {
            __nv_bfloat16 h, l;
            split2(tile[tx][i], h, l);
            size_t o = (size_t)n * K + k0 + tx;
            oh[o] = h; ol[o] = l;
        }
    }
}

// ---------------- small precompute ------------------
__global__ void prep_kernel(const float* __restrict__ theta_raw,
                            const float* __restrict__ wint_raw,
                            const float* __restrict__ decay)
{
    int i = threadIdx.x;
    if (i < PK*PH) {
        g_theta[i] = 0.001f + 2.999f * sigmoidf_(theta_raw[i]);
        float e = expf(wint_raw[i]);
        g_wint[i] = e / (e + 1e-6f);
    }
    if (i < PK) g_slope[i] = softplusf_(decay[i]);
}

// ---------------- fused conv+silu+stack -------------
// reads z_pre (g_buf0), writes stack -> g_z, q -> g_q
__global__ void convstack_kernel(const float* __restrict__ conv_w,
                                 const float* __restrict__ score_scale,
                                 const float* __restrict__ score_bias,
                                 const float* __restrict__ phase_scale)
{
    __shared__ float s_pw[PK];
    int tok = blockIdx.x;
    int tid = threadIdx.x;
    int l = tok & (PL-1);
    long long zb = (long long)tok * DIM_CONV;

    auto conv1 = [&](int c) -> float {
        float acc = 0.f;
#pragma unroll
        for (int tt = 0; tt < PKSIZE; tt++) {
            int dl = l + tt - (PKSIZE-1);
            if (dl >= 0)
                acc += g_buf0[zb + (long long)(tt - (PKSIZE-1)) * DIM_CONV + c]
                       * conv_w[tt*DIM_CONV + c];
        }
        return acc * sigmoidf_(acc);
    };

    if (tid < PK) {
        float s  = conv1(DIM_MEM + tid);
        float u  = score_scale[tid]*s + score_bias[tid];
        float sp = softplusf_(u);
        float tw = expf(-g_slope[tid] * (float)(PMAXLEN-1 - l));
        float p  = fminf(fmaxf(sp*tw, 1e-4f), 5000.f);
        s_pw[tid] = p;
        g_z[zb + tid] = p;
    }
    __syncthreads();

    for (int i = tid; i < DIM_MEM; i += blockDim.x) {
        int k = i >> 6;
        float kv = conv1(i);
        float ks = kv * phase_scale[k];
        float phi = ks / (1.f + fabsf(ks)) * g_theta[i];
        float sn, cs;
        sincosf(phi, &sn, &cs);
        float kvw = kv * s_pw[k];
        g_z[zb + PK + i]           = kvw * cs;
        g_z[zb + PK + DIM_MEM + i] = kvw * sn;
    }
    for (int i = tid; i < 768; i += blockDim.x) {
        g_q[(long long)tok * 768 + i] = conv1(DIM_MEM_TOT + i);
    }
}

// ---------------- chunked scan (over g_z) -----------
__global__ void scan_partial_kernel()
{
    int c = blockIdx.x * blockDim.x + threadIdx.x;
    if (c >= DIM_CONV) return;
    int chunk = blockIdx.y;
    int b = blockIdx.z;

    long long base = ((long long)(b*PL + chunk*CHROWS)) * DIM_CONV + c;
    float run = 0.f;
#pragma unroll 4
    for (int r = 0; r < CHROWS; r++) {
        long long p = base + (long long)r * DIM_CONV;
        run += g_z[p];
        g_z[p] = run;
    }
    g_csum[((long long)(b*NCHUNK + chunk))*DIM_CONV + c] = run;
}

__global__ void scan_offsets_kernel()
{
    int i = blockIdx.x * blockDim.x + threadIdx.x;
    if (i >= PB*DIM_CONV) return;
    int b = i / DIM_CONV;
    int c = i - b*DIM_CONV;
    float off = 0.f;
#pragma unroll
    for (int ch = 0; ch < NCHUNK; ch++) {
        long long idx = ((long long)(b*NCHUNK + ch))*DIM_CONV + c;
        float t = g_csum[idx];
        g_csum[idx] = off;
        off += t;
    }
}

// ---------------- epilogue 1 ------------------------
__global__ void epilogue1_kernel(const float* __restrict__ gnw)
{
    __shared__ float s_inv[PK];
    __shared__ float s_red[8];
    int tok = blockIdx.x;
    int tid = threadIdx.x;
    int l = tok & (PL-1);
    int b = tok >> 12;
    int chunk = l >> 9;

    long long zb  = (long long)tok * DIM_CONV;
    long long ob  = ((long long)(b*NCHUNK + chunk)) * DIM_CONV;
    long long gb  = (long long)tok * OUT_CPLX;
    long long qb  = (long long)tok * 768;

    if (tid < PK) {
        float den = g_z[zb + tid] + g_csum[ob + tid];
        s_inv[tid] = 1.f / fmaxf(den, 1e-4f);
    }
    __syncthreads();

    float hvals[OUT_CPLX/256];
    float sumsq = 0.f;
#pragma unroll
    for (int it = 0; it < OUT_CPLX/256; it++) {
        int f = tid + it*256;
        int k = f >> 7;
        int j = f & 127;
        int h = j & 63;
        int is_im = j >> 6;
        int idx = k*PH + h;

        float re_acc = g_z[zb + PK + idx]           + g_csum[ob + PK + idx];
        float im_acc = g_z[zb + PK + DIM_MEM + idx] + g_csum[ob + PK + DIM_MEM + idx];
        float sre = re_acc * s_inv[k];
        float sim = im_acc * s_inv[k];
        int kq = k >> 1;
        float qre = g_q[qb + (kq*PH + h)*2];
        float qim = g_q[qb + (kq*PH + h)*2 + 1];
        float val;
        if (!is_im) val = (sre*qre + sim*qim);
        else        val = (sim*qre - sre*qim);
        val *= 0.125f * g_wint[idx];

        float gv = g_gate[gb + f];
        float hv = val * (gv * sigmoidf_(gv));
        hvals[it] = hv;
        sumsq += hv*hv;
    }
#pragma unroll
    for (int o = 16; o > 0; o >>= 1) sumsq += __shfl_xor_sync(0xffffffff, sumsq, o);
    if ((tid & 31) == 0) s_red[tid >> 5] = sumsq;
    __syncthreads();
    if (tid < 32) {
        float v = (tid < 8) ? s_red[tid] : 0.f;
#pragma unroll
        for (int o = 4; o > 0; o >>= 1) v += __shfl_xor_sync(0xffffffff, v, o);
        if (tid == 0) s_red[0] = v;
    }
    __syncthreads();
    float rms = rsqrtf(s_red[0] / (float)OUT_CPLX + 1e-6f);

#pragma unroll
    for (int it = 0; it < OUT_CPLX/256; it++) {
        int f = tid + it*256;
        float v = hvals[it] * rms * gnw[f];
        __nv_bfloat16 h, lo;
        split2(v, h, lo);
        g_onh[gb + f] = h;
        g_onl[gb + f] = lo;
    }
}

// ---------------- readout gating -> bf16 split ------
__global__ void ygate_kernel()
{
    int j = blockIdx.x * blockDim.x + threadIdx.x;
    if (j >= PK*DIM_EXPAND) return;
    int tok = blockIdx.y;
    int k = j / DIM_EXPAND;
    int n = j - k*DIM_EXPAND;
    long long yb = (long long)tok * (PK*384);
    float v = g_yraw[yb + k*384 + n];
    float g = g_yraw[yb + k*384 + DIM_EXPAND + n];
    float r = v * sigmoidf_(g);
    __nv_bfloat16 h, l;
    split2(r, h, l);
    size_t o = (size_t)tok*(PK*DIM_EXPAND) + j;
    g_yh[o] = h;
    g_yl[o] = l;
}

// ---------------- launcher --------------------------
extern "C" void kernel_launch(void* const* d_in, const int* in_sizes, int n_in,
                              void* d_out, int out_size)
{
    const float* x        = (const float*)d_in[0];
    const float* W_in     = (const float*)d_in[1];
    const float* conv_w   = (const float*)d_in[2];
    const float* theta_raw= (const float*)d_in[3];
    const float* wint_raw = (const float*)d_in[4];
    const float* decay    = (const float*)d_in[5];
    const float* sscale   = (const float*)d_in[6];
    const float* sbias    = (const float*)d_in[7];
    const float* pscale   = (const float*)d_in[8];
    const float* gnw      = (const float*)d_in[9];
    const float* W_read   = (const float*)d_in[10];
    const float* W_gate   = (const float*)d_in[11];
    const float* W_out    = (const float*)d_in[12];
    float* out            = (float*)d_out;

    float *p_buf0, *p_gate, *p_yraw;
    __nv_bfloat16 *p_xh, *p_xl, *p_Winh, *p_Winl, *p_Wgh, *p_Wgl;
    __nv_bfloat16 *p_Woh, *p_Wol, *p_Wrh, *p_Wrl, *p_onh, *p_onl, *p_yh, *p_yl;
    cudaGetSymbolAddress((void**)&p_buf0, g_buf0);
    cudaGetSymbolAddress((void**)&p_gate, g_gate);
    cudaGetSymbolAddress((void**)&p_yraw, g_yraw);
    cudaGetSymbolAddress((void**)&p_xh,   g_xh);
    cudaGetSymbolAddress((void**)&p_xl,   g_xl);
    cudaGetSymbolAddress((void**)&p_Winh, g_Winh);
    cudaGetSymbolAddress((void**)&p_Winl, g_Winl);
    cudaGetSymbolAddress((void**)&p_Wgh,  g_Wgh);
    cudaGetSymbolAddress((void**)&p_Wgl,  g_Wgl);
    cudaGetSymbolAddress((void**)&p_Woh,  g_Woh);
    cudaGetSymbolAddress((void**)&p_Wol,  g_Wol);
    cudaGetSymbolAddress((void**)&p_Wrh,  g_Wrh);
    cudaGetSymbolAddress((void**)&p_Wrl,  g_Wrl);
    cudaGetSymbolAddress((void**)&p_onh,  g_onh);
    cudaGetSymbolAddress((void**)&p_onl,  g_onl);
    cudaGetSymbolAddress((void**)&p_yh,   g_yh);
    cudaGetSymbolAddress((void**)&p_yl,   g_yl);

    cudaFuncSetAttribute(gemm_mma_kernel,
                         cudaFuncAttributeMaxDynamicSharedMemorySize, GSMEM);

    // 0) precompute + conversions
    prep_kernel<<<1, 768>>>(theta_raw, wint_raw, decay);
    {
        size_t n = (size_t)NTOK * PD;
        split_x_kernel<<<(unsigned)((n + 255) / 256), 256>>>(x);
    }
    {
        dim3 blk(32, 8);
        tsplit_kernel<<<dim3((DIM_CONV+31)/32, PD/32, 1),  blk>>>(W_in,  p_Winh, p_Winl, PD, DIM_CONV);
        tsplit_kernel<<<dim3(OUT_CPLX/32,      PD/32, 1),  blk>>>(W_gate, p_Wgh, p_Wgl, PD, OUT_CPLX);
        tsplit_kernel<<<dim3(PD/32,          2304/32, 1),  blk>>>(W_out, p_Woh, p_Wol, 2304, PD);
        tsplit_kernel<<<dim3(384/32,          128/32, PK), blk>>>(W_read, p_Wrh, p_Wrl, 128, 384);
    }

    // 1) z_pre = x @ W_in   [16384,1548]
    gemm_mma_kernel<<<dim3((DIM_CONV + GBN - 1)/GBN, NTOK/GBM, 1), 256, GSMEM>>>(
        NTOK, DIM_CONV, PD, p_xh, p_xl, PD, 0, p_Winh, p_Winl, PD, 0, p_buf0, DIM_CONV, 0);

    // 2+3) fused conv+silu+stack
    convstack_kernel<<<NTOK, 256>>>(conv_w, sscale, sbias, pscale);

    // 4) chunked cumsum over g_z
    scan_partial_kernel<<<dim3((DIM_CONV+127)/128, NCHUNK, PB), 128>>>();
    scan_offsets_kernel<<<(PB*DIM_CONV+255)/256, 256>>>();

    // 5) gate = x @ W_gate  [16384,1536]
    gemm_mma_kernel<<<dim3(OUT_CPLX/GBN, NTOK/GBM, 1), 256, GSMEM>>>(
        NTOK, OUT_CPLX, PD, p_xh, p_xl, PD, 0, p_Wgh, p_Wgl, PD, 0, p_gate, OUT_CPLX, 0);

    // 6) epilogue: out_flat + gated rmsnorm -> bf16 split
    epilogue1_kernel<<<NTOK, 256>>>(gnw);

    // 7) batched readout (12 batches)
    gemm_mma_kernel<<<dim3(384/GBN, NTOK/GBM, PK), 256, GSMEM>>>(
        NTOK, 384, 128,
        p_onh, p_onl, OUT_CPLX, 128,
        p_Wrh, p_Wrl, 128, (long long)384*128,
        p_yraw, PK*384, 384);

    // 8) gating -> bf16 split y
    ygate_kernel<<<dim3((PK*DIM_EXPAND+255)/256, NTOK), 256>>>();

    // 9) final: out = y @ W_out  [16384,768]
    gemm_mma_kernel<<<dim3(PD/GBN, NTOK/GBM, 1), 256, GSMEM>>>(
        NTOK, PD, PK*DIM_EXPAND, p_yh, p_yl, PK*DIM_EXPAND, 0,
        p_Woh, p_Wol, PK*DIM_EXPAND, 0, out, PD, 0);
}